// round 10
// baseline (speedup 1.0000x reference)
#include <cuda_runtime.h>
#include <cuda_fp16.h>
#include <math.h>
#include <stdint.h>

// ---------------------------------------------------------------------------
// Problem dims
// ---------------------------------------------------------------------------
#define M_ROWS  8192      // 4 * 2048
#define N_ATOMS 16384
#define DM      1024
#define LOG2E   1.4426950408889634f
#define NEG_H   (-60000.0f)   // masked score in fp16 domain (log2-scaled)

// ---------------------------------------------------------------------------
// Scratch (__device__ globals; allocation APIs are forbidden)
// ---------------------------------------------------------------------------
__device__ __half  g_scores[(size_t)M_ROWS * N_ATOMS];     // 256 MB fp16
__device__ __half  g_Xf[(size_t)M_ROWS * DM];
__device__ __half  g_Df[(size_t)N_ATOMS * DM];             // dict fp16 K-major
__device__ __half  g_DTf[(size_t)DM * N_ATOMS];            // dict^T fp16
__device__ __half  g_Wf[(size_t)M_ROWS * N_ATOMS];         // 256 MB fp16
__device__ float   g_inv[M_ROWS];
__device__ int     g_top4[M_ROWS * 4];

// ---------------------------------------------------------------------------
// Low-level helpers (sm_80+ baseline PTX only — NO tcgen05 on plain sm_103)
// ---------------------------------------------------------------------------
__device__ __forceinline__ uint32_t smem_to_u32(const void* p) {
    uint32_t a;
    asm("{ .reg .u64 t; cvta.to.shared.u64 t, %1; cvt.u32.u64 %0, t; }"
        : "=r"(a) : "l"(p));
    return a;
}

#define CP16(dst, src) \
    asm volatile("cp.async.cg.shared.global [%0], [%1], 16;" \
                 :: "r"(dst), "l"(src) : "memory")
#define CP_COMMIT() asm volatile("cp.async.commit_group;" ::: "memory")
#define CP_WAIT2()  asm volatile("cp.async.wait_group 2;"  ::: "memory")

#define LDSM4(r0, r1, r2, r3, addr) \
    asm volatile("ldmatrix.sync.aligned.m8n8.x4.shared.b16 {%0,%1,%2,%3}, [%4];" \
        : "=r"(r0), "=r"(r1), "=r"(r2), "=r"(r3) : "r"(addr))

__device__ __forceinline__ void mma16816_f16(float* c, const uint32_t* a,
                                             const uint32_t* b) {
    asm volatile(
        "mma.sync.aligned.m16n8k16.row.col.f32.f16.f16.f32 "
        "{%0,%1,%2,%3}, {%4,%5,%6,%7}, {%8,%9}, {%0,%1,%2,%3};"
        : "+f"(c[0]), "+f"(c[1]), "+f"(c[2]), "+f"(c[3])
        : "r"(a[0]), "r"(a[1]), "r"(a[2]), "r"(a[3]), "r"(b[0]), "r"(b[1]));
}

__device__ __forceinline__ float ex2f(float x) {
    float y;
    asm("ex2.approx.ftz.f32 %0, %1;" : "=f"(y) : "f"(x));
    return y;
}

// ---------------------------------------------------------------------------
// Conversion kernels
// ---------------------------------------------------------------------------
__global__ __launch_bounds__(256) void to_f16_kernel(
    const float* __restrict__ src, __half* __restrict__ dst, int n4)
{
    int i = blockIdx.x * blockDim.x + threadIdx.x;
    if (i >= n4) return;
    float4 v = reinterpret_cast<const float4*>(src)[i];
    ushort4 hv;
    hv.x = __half_as_ushort(__float2half_rn(v.x));
    hv.y = __half_as_ushort(__float2half_rn(v.y));
    hv.z = __half_as_ushort(__float2half_rn(v.z));
    hv.w = __half_as_ushort(__float2half_rn(v.w));
    reinterpret_cast<ushort4*>(dst)[i] = hv;
}

// dict [N_ATOMS][DM] fp32 -> DTf [DM][N_ATOMS] fp16
__global__ __launch_bounds__(256) void transpose_f16_kernel(
    const float* __restrict__ dict, __half* __restrict__ DTf)
{
    __shared__ float t[32][33];
    const int bx = blockIdx.x;
    const int by = blockIdx.y;
    const int tx = threadIdx.x;
    const int ty = threadIdx.y;
    #pragma unroll
    for (int k = 0; k < 32; k += 8)
        t[ty + k][tx] = dict[(size_t)(by * 32 + ty + k) * DM + bx * 32 + tx];
    __syncthreads();
    #pragma unroll
    for (int k = 0; k < 32; k += 8) {
        size_t o = (size_t)(bx * 32 + ty + k) * N_ATOMS + by * 32 + tx;
        DTf[o] = __float2half_rn(t[tx][ty + k]);
    }
}

// ---------------------------------------------------------------------------
// Unified 1-term fp16 GEMM via ldmatrix + mma.sync, 4-stage cp.async pipe.
// out tile 128x128 = A[M,K] · B[N,K]^T
// MASK=true : out is __half, masked -> NEG_H, scaled by LOG2E (scores)
// MASK=false: out is float, row scaled by invp[row] (recon)
// 256 threads = 8 warps (2m x 4n) of 64x32 each, BK=32.
// smem rows: 64B data + 16B pad (80B) — conflict-free LDSM phases.
// ---------------------------------------------------------------------------
#define ROWB     80
#define TILE_B   (128 * ROWB)          // 10240
#define STAGE    (2 * TILE_B)          // 20480
#define NSTAGES  4
#define SMEMG    (NSTAGES * STAGE)     // 81920

template <bool MASK>
__global__ __launch_bounds__(256, 2) void gemm_f16(
    const __half* __restrict__ A, const __half* __restrict__ B, int Kdim,
    const int* __restrict__ mask, const float* __restrict__ invp,
    void* __restrict__ outp, int out_ld)
{
    extern __shared__ char smem[];
    const uint32_t sbase = smem_to_u32(smem);
    const int tid  = threadIdx.x;
    const int warp = tid >> 5;
    const int lane = tid & 31;
    const int bm = blockIdx.y * 128;
    const int bn = blockIdx.x * 128;
    const int wm = (warp & 1) * 64;   // 2 m-warps
    const int wn = (warp >> 1) * 32;  // 4 n-warps

    // ldmatrix per-thread address components
    const int a_row = wm + (lane & 15);
    const int a_kh  = (lane >> 4) * 16;
    const int b_row = wn + ((lane >> 4) << 3) + (lane & 7);
    const int b_kh  = ((lane >> 3) & 1) * 16;

    float acc[4][4][4];
    #pragma unroll
    for (int mt = 0; mt < 4; mt++)
        #pragma unroll
        for (int nt = 0; nt < 4; nt++)
            #pragma unroll
            for (int r = 0; r < 4; r++) acc[mt][nt][r] = 0.0f;

    #define ISSUEG(cc, buf) do { \
        const int k0_ = (cc) << 5; \
        _Pragma("unroll") \
        for (int p = 0; p < 2; p++) { \
            const int v_   = tid + p * 256; \
            const int row_ = v_ >> 2; \
            const int c16_ = v_ & 3; \
            const uint32_t dst_ = sbase + (buf) * STAGE \
                                + row_ * ROWB + c16_ * 16; \
            const size_t ga_ = (size_t)(bm + row_) * Kdim + k0_ + c16_ * 8; \
            const size_t gb_ = (size_t)(bn + row_) * Kdim + k0_ + c16_ * 8; \
            CP16(dst_ + 0 * TILE_B, A + ga_); \
            CP16(dst_ + 1 * TILE_B, B + gb_); \
        } \
        CP_COMMIT(); \
    } while (0)

    ISSUEG(0, 0);
    ISSUEG(1, 1);
    ISSUEG(2, 2);

    const int NC = Kdim >> 5;
    for (int c = 0; c < NC; c++) {
        CP_WAIT2();          // chunk c resident (<=2 younger groups pending)
        __syncthreads();     // all warps past compute of chunk c-1
        if (c + 3 < NC) ISSUEG(c + 3, (c + 3) & 3);

        const uint32_t sA = sbase + (c & 3) * STAGE;
        const uint32_t sB = sA + TILE_B;

        #pragma unroll
        for (int ks = 0; ks < 2; ks++) {
            const uint32_t kb0 = ks * 32;

            uint32_t a[4][4], b[4][2];
            #pragma unroll
            for (int mt = 0; mt < 4; mt++) {
                const uint32_t ad = sA + (a_row + mt * 16) * ROWB + a_kh + kb0;
                LDSM4(a[mt][0], a[mt][1], a[mt][2], a[mt][3], ad);
            }
            #pragma unroll
            for (int p = 0; p < 2; p++) {
                const uint32_t bd = sB + (b_row + p * 16) * ROWB + b_kh + kb0;
                LDSM4(b[2 * p][0], b[2 * p][1], b[2 * p + 1][0], b[2 * p + 1][1], bd);
            }
            #pragma unroll
            for (int nt = 0; nt < 4; nt++)
                #pragma unroll
                for (int mt = 0; mt < 4; mt++)
                    mma16816_f16(acc[mt][nt], a[mt], b[nt]);
        }
    }
    #undef ISSUEG

    // Epilogue
    const int lr = lane >> 2;
    #pragma unroll
    for (int mt = 0; mt < 4; mt++) {
        #pragma unroll
        for (int half = 0; half < 2; half++) {
            const int rloc = bm + wm + mt * 16 + lr + half * 8;
            float inv = 1.0f;
            if (!MASK) inv = invp[rloc];
            const size_t rg = (size_t)rloc;
            #pragma unroll
            for (int nt = 0; nt < 4; nt++) {
                const size_t o = rg * (size_t)out_ld
                               + (bn + wn + nt * 8 + (lane & 3) * 2);
                if (MASK) {
                    int2 mv = *reinterpret_cast<const int2*>(mask + o);
                    float2 v;
                    v.x = mv.x ? acc[mt][nt][half * 2 + 0] * LOG2E : NEG_H;
                    v.y = mv.y ? acc[mt][nt][half * 2 + 1] * LOG2E : NEG_H;
                    *reinterpret_cast<__half2*>((__half*)outp + o) =
                        __float22half2_rn(v);
                } else {
                    float2 v;
                    v.x = acc[mt][nt][half * 2 + 0] * inv;
                    v.y = acc[mt][nt][half * 2 + 1] * inv;
                    *reinterpret_cast<float2*>((float*)outp + o) = v;
                }
            }
        }
    }
}

// ---------------------------------------------------------------------------
// Fused softmax over fp16 log2-scaled scores. Pass 1: top-4 + max.
// Pass 2: w = 2^(s - max), accumulate sum, write fp16 unnormalized weights.
// inv[row] = 1/sum applied in recon epilogue.
// ---------------------------------------------------------------------------
#define BETTER(v, i, V, I) ((v) > (V) || ((v) == (V) && (i) < (I)))

__global__ __launch_bounds__(256) void softmax_top4_kernel(
    const __half* __restrict__ S, __half* __restrict__ Wf,
    float* __restrict__ invp, int* __restrict__ top4)
{
    const int row = blockIdx.x;
    const __half* s = S + (size_t)row * N_ATOMS;
    const int tid = threadIdx.x;

    __shared__ float sv[4][256];
    __shared__ int   si[4][256];

    float tv[4] = {-INFINITY, -INFINITY, -INFINITY, -INFINITY};
    int   ti[4] = {0x7fffffff, 0x7fffffff, 0x7fffffff, 0x7fffffff};

    #define INS4(v, i) do { \
        float v_ = (v); int i_ = (i); \
        if (BETTER(v_, i_, tv[3], ti[3])) { \
            tv[3] = v_; ti[3] = i_; \
            if (BETTER(tv[3], ti[3], tv[2], ti[2])) { \
                float tv_ = tv[2]; int ti_ = ti[2]; \
                tv[2] = tv[3]; ti[2] = ti[3]; tv[3] = tv_; ti[3] = ti_; \
                if (BETTER(tv[2], ti[2], tv[1], ti[1])) { \
                    tv_ = tv[1]; ti_ = ti[1]; \
                    tv[1] = tv[2]; ti[1] = ti[2]; tv[2] = tv_; ti[2] = ti_; \
                    if (BETTER(tv[1], ti[1], tv[0], ti[0])) { \
                        tv_ = tv[0]; ti_ = ti[0]; \
                        tv[0] = tv[1]; ti[0] = ti[1]; tv[1] = tv_; ti[1] = ti_; \
                    } \
                } \
            } \
        } \
    } while (0)

    for (int c0 = tid * 8; c0 < N_ATOMS; c0 += 2048) {
        uint4 u = *reinterpret_cast<const uint4*>(s + c0);
        float2 f0 = __half22float2(*reinterpret_cast<__half2*>(&u.x));
        float2 f1 = __half22float2(*reinterpret_cast<__half2*>(&u.y));
        float2 f2 = __half22float2(*reinterpret_cast<__half2*>(&u.z));
        float2 f3 = __half22float2(*reinterpret_cast<__half2*>(&u.w));
        INS4(f0.x, c0 + 0); INS4(f0.y, c0 + 1);
        INS4(f1.x, c0 + 2); INS4(f1.y, c0 + 3);
        INS4(f2.x, c0 + 4); INS4(f2.y, c0 + 5);
        INS4(f3.x, c0 + 6); INS4(f3.y, c0 + 7);
    }
    #pragma unroll
    for (int j = 0; j < 4; j++) { sv[j][tid] = tv[j]; si[j][tid] = ti[j]; }
    __syncthreads();
    for (int off = 128; off > 0; off >>= 1) {
        if (tid < off) {
            #pragma unroll
            for (int j = 0; j < 4; j++) { tv[j] = sv[j][tid]; ti[j] = si[j][tid]; }
            #pragma unroll
            for (int j = 0; j < 4; j++)
                INS4(sv[j][tid + off], si[j][tid + off]);
            #pragma unroll
            for (int j = 0; j < 4; j++) { sv[j][tid] = tv[j]; si[j][tid] = ti[j]; }
        }
        __syncthreads();
    }
    #undef INS4

    const float rmax = sv[0][0];
    if (tid < 4) top4[row * 4 + tid] = si[tid][0];
    __syncthreads();

    // Exp pass: compute, write fp16 weights, accumulate sum
    __half* wf = Wf + (size_t)row * N_ATOMS;
    float lsum = 0.0f;
    for (int c0 = tid * 8; c0 < N_ATOMS; c0 += 2048) {
        uint4 u = *reinterpret_cast<const uint4*>(s + c0);
        float2 f0 = __half22float2(*reinterpret_cast<__half2*>(&u.x));
        float2 f1 = __half22float2(*reinterpret_cast<__half2*>(&u.y));
        float2 f2 = __half22float2(*reinterpret_cast<__half2*>(&u.z));
        float2 f3 = __half22float2(*reinterpret_cast<__half2*>(&u.w));
        float w0 = ex2f(f0.x - rmax), w1 = ex2f(f0.y - rmax);
        float w2 = ex2f(f1.x - rmax), w3 = ex2f(f1.y - rmax);
        float w4 = ex2f(f2.x - rmax), w5 = ex2f(f2.y - rmax);
        float w6 = ex2f(f3.x - rmax), w7 = ex2f(f3.y - rmax);
        lsum += ((w0 + w1) + (w2 + w3)) + ((w4 + w5) + (w6 + w7));
        uint4 o;
        *reinterpret_cast<__half2*>(&o.x) = __float22half2_rn(make_float2(w0, w1));
        *reinterpret_cast<__half2*>(&o.y) = __float22half2_rn(make_float2(w2, w3));
        *reinterpret_cast<__half2*>(&o.z) = __float22half2_rn(make_float2(w4, w5));
        *reinterpret_cast<__half2*>(&o.w) = __float22half2_rn(make_float2(w6, w7));
        *reinterpret_cast<uint4*>(wf + c0) = o;
    }
    sv[0][tid] = lsum;
    __syncthreads();
    for (int off = 128; off > 0; off >>= 1) {
        if (tid < off) sv[0][tid] += sv[0][tid + off];
        __syncthreads();
    }
    if (tid == 0) invp[row] = 1.0f / sv[0][0];
}

// ---------------------------------------------------------------------------
// Exact fp32 argmax rescue over 4 candidates. One warp per row.
// ---------------------------------------------------------------------------
__global__ __launch_bounds__(256) void argmax_rescue4_kernel(
    const float* __restrict__ X, const float* __restrict__ Dict,
    const int* __restrict__ mask, const int* __restrict__ top4,
    float* __restrict__ argmax_out)
{
    const int row = blockIdx.x * 8 + (threadIdx.x >> 5);
    const int lid = threadIdx.x & 31;
    int ci[4];
    #pragma unroll
    for (int j = 0; j < 4; j++) ci[j] = top4[row * 4 + j];

    const float* x = X + (size_t)row * DM;
    float sc[4] = {0.0f, 0.0f, 0.0f, 0.0f};
    for (int k = lid * 4; k < DM; k += 128) {
        float4 xv = *reinterpret_cast<const float4*>(x + k);
        #pragma unroll
        for (int j = 0; j < 4; j++) {
            float4 d = *reinterpret_cast<const float4*>(
                Dict + (size_t)ci[j] * DM + k);
            sc[j] += xv.x * d.x + xv.y * d.y + xv.z * d.z + xv.w * d.w;
        }
    }
    #pragma unroll
    for (int off = 16; off > 0; off >>= 1)
        #pragma unroll
        for (int j = 0; j < 4; j++)
            sc[j] += __shfl_xor_sync(0xffffffffu, sc[j], off);

    if (lid == 0) {
        const int* mrow = mask + (size_t)row * N_ATOMS;
        float bv = -INFINITY; int bi = 0x7fffffff;
        #pragma unroll
        for (int j = 0; j < 4; j++) {
            float v = mrow[ci[j]] ? sc[j] : -1e9f;
            if (BETTER(v, ci[j], bv, bi)) { bv = v; bi = ci[j]; }
        }
        argmax_out[row] = (float)bi;
    }
}

// ---------------------------------------------------------------------------
// Launch
// ---------------------------------------------------------------------------
extern "C" void kernel_launch(void* const* d_in, const int* in_sizes, int n_in,
                              void* d_out, int out_size)
{
    const float* X    = (const float*)d_in[0];
    const float* Dict = (const float*)d_in[1];
    const int*   mask = (const int*)d_in[2];
    float* out = (float*)d_out;

    __half *scores, *Xf, *Df, *DTf, *Wf;
    cudaGetSymbolAddress((void**)&scores, g_scores);
    cudaGetSymbolAddress((void**)&Xf, g_Xf);
    cudaGetSymbolAddress((void**)&Df, g_Df);
    cudaGetSymbolAddress((void**)&DTf, g_DTf);
    cudaGetSymbolAddress((void**)&Wf, g_Wf);
    float* invp; cudaGetSymbolAddress((void**)&invp, g_inv);
    int* top4; cudaGetSymbolAddress((void**)&top4, g_top4);

    float* recon_out  = out;
    float* argmax_out = out + (size_t)M_ROWS * DM;

    static bool attr_set = false;
    if (!attr_set) {
        cudaFuncSetAttribute(gemm_f16<true>,
                             cudaFuncAttributeMaxDynamicSharedMemorySize, SMEMG);
        cudaFuncSetAttribute(gemm_f16<false>,
                             cudaFuncAttributeMaxDynamicSharedMemorySize, SMEMG);
        attr_set = true;
    }

    // 1) fp16 conversions: X, dict (K-major), dict^T
    {
        int n4x = (M_ROWS * DM) / 4;
        to_f16_kernel<<<(n4x + 255) / 256, 256>>>(X, Xf, n4x);
        int n4d = (N_ATOMS * DM) / 4;
        to_f16_kernel<<<(n4d + 255) / 256, 256>>>(Dict, Df, n4d);
        dim3 grid(DM / 32, N_ATOMS / 32), blk(32, 8);
        transpose_f16_kernel<<<grid, blk>>>(Dict, DTf);
    }

    // 2) scores*log2e (fp16) = (Xf · Df^T)*log2e with fused mask
    {
        dim3 grid(N_ATOMS / 128, M_ROWS / 128);
        gemm_f16<true><<<grid, 256, SMEMG>>>(
            Xf, Df, DM, mask, nullptr, scores, N_ATOMS);
    }

    // 3) fused softmax: top-4, exp via MUFU, unnormalized fp16 weights + inv
    softmax_top4_kernel<<<M_ROWS, 256>>>(scores, Wf, invp, top4);

    // 4) exact fp32 argmax among the four candidates
    argmax_rescue4_kernel<<<M_ROWS / 8, 256>>>(X, Dict, mask, top4, argmax_out);

    // 5) reconstruction = (Wf · DTf) * inv[row]
    {
        dim3 grid(DM / 128, M_ROWS / 128);
        gemm_f16<false><<<grid, 256, SMEMG>>>(
            Wf, DTf, N_ATOMS, nullptr, invp, recon_out, DM);
    }
}

// round 11
// speedup vs baseline: 1.3074x; 1.3074x over previous
#include <cuda_runtime.h>
#include <cuda_fp16.h>
#include <math.h>
#include <stdint.h>

// ---------------------------------------------------------------------------
// Problem dims
// ---------------------------------------------------------------------------
#define M_ROWS  8192      // 4 * 2048
#define N_ATOMS 16384
#define DM      1024
#define LOG2E   1.4426950408889634f
#define NEG_H   (-60000.0f)   // masked score in fp16 domain (log2-scaled)
#define DELTA   0.008f        // argmax candidate threshold (log2 units)
#define MAXCAND 16

// ---------------------------------------------------------------------------
// Scratch (__device__ globals; allocation APIs are forbidden)
// ---------------------------------------------------------------------------
__device__ __half  g_scores[(size_t)M_ROWS * N_ATOMS];     // 256 MB fp16
__device__ __half  g_Xf[(size_t)M_ROWS * DM];
__device__ __half  g_Df[(size_t)N_ATOMS * DM];             // dict fp16 K-major
__device__ __half  g_DTf[(size_t)DM * N_ATOMS];            // dict^T fp16
__device__ __half  g_Wf[(size_t)M_ROWS * N_ATOMS];         // 256 MB fp16
__device__ float   g_inv[M_ROWS];
__device__ int     g_cand[M_ROWS * (MAXCAND + 1)];         // [cnt, idx...]

// ---------------------------------------------------------------------------
// Low-level helpers (sm_80+ baseline PTX only — NO tcgen05 on plain sm_103)
// ---------------------------------------------------------------------------
__device__ __forceinline__ uint32_t smem_to_u32(const void* p) {
    uint32_t a;
    asm("{ .reg .u64 t; cvta.to.shared.u64 t, %1; cvt.u32.u64 %0, t; }"
        : "=r"(a) : "l"(p));
    return a;
}

#define CP16(dst, src) \
    asm volatile("cp.async.cg.shared.global [%0], [%1], 16;" \
                 :: "r"(dst), "l"(src) : "memory")
#define CP_COMMIT() asm volatile("cp.async.commit_group;" ::: "memory")
#define CP_WAIT1()  asm volatile("cp.async.wait_group 1;"  ::: "memory")

#define LDSM4(r0, r1, r2, r3, addr) \
    asm volatile("ldmatrix.sync.aligned.m8n8.x4.shared.b16 {%0,%1,%2,%3}, [%4];" \
        : "=r"(r0), "=r"(r1), "=r"(r2), "=r"(r3) : "r"(addr))

__device__ __forceinline__ void mma16816_f16(float* c, const uint32_t* a,
                                             const uint32_t* b) {
    asm volatile(
        "mma.sync.aligned.m16n8k16.row.col.f32.f16.f16.f32 "
        "{%0,%1,%2,%3}, {%4,%5,%6,%7}, {%8,%9}, {%0,%1,%2,%3};"
        : "+f"(c[0]), "+f"(c[1]), "+f"(c[2]), "+f"(c[3])
        : "r"(a[0]), "r"(a[1]), "r"(a[2]), "r"(a[3]), "r"(b[0]), "r"(b[1]));
}

__device__ __forceinline__ float ex2f(float x) {
    float y;
    asm("ex2.approx.ftz.f32 %0, %1;" : "=f"(y) : "f"(x));
    return y;
}

// ---------------------------------------------------------------------------
// Conversion kernels
// ---------------------------------------------------------------------------
__global__ __launch_bounds__(256) void to_f16_kernel(
    const float* __restrict__ src, __half* __restrict__ dst, int n4)
{
    int i = blockIdx.x * blockDim.x + threadIdx.x;
    if (i >= n4) return;
    float4 v = reinterpret_cast<const float4*>(src)[i];
    ushort4 hv;
    hv.x = __half_as_ushort(__float2half_rn(v.x));
    hv.y = __half_as_ushort(__float2half_rn(v.y));
    hv.z = __half_as_ushort(__float2half_rn(v.z));
    hv.w = __half_as_ushort(__float2half_rn(v.w));
    reinterpret_cast<ushort4*>(dst)[i] = hv;
}

// dict [N_ATOMS][DM] fp32 -> DTf [DM][N_ATOMS] fp16
__global__ __launch_bounds__(256) void transpose_f16_kernel(
    const float* __restrict__ dict, __half* __restrict__ DTf)
{
    __shared__ float t[32][33];
    const int bx = blockIdx.x;
    const int by = blockIdx.y;
    const int tx = threadIdx.x;
    const int ty = threadIdx.y;
    #pragma unroll
    for (int k = 0; k < 32; k += 8)
        t[ty + k][tx] = dict[(size_t)(by * 32 + ty + k) * DM + bx * 32 + tx];
    __syncthreads();
    #pragma unroll
    for (int k = 0; k < 32; k += 8) {
        size_t o = (size_t)(bx * 32 + ty + k) * N_ATOMS + by * 32 + tx;
        DTf[o] = __float2half_rn(t[tx][ty + k]);
    }
}

// ---------------------------------------------------------------------------
// Unified 1-term fp16 GEMM via ldmatrix + mma.sync, BK=64, 3-stage cp.async.
// out tile 128x128 = A[M,K] · B[N,K]^T
// MASK=true : out is __half, masked -> NEG_H, scaled by LOG2E (scores)
// MASK=false: out is float, row scaled by invp[row] (recon)
// 128 threads = 4 warps (2x2) of 64x64.
// smem rows: 128B data + 16B pad (144B) — conflict-free LDSM phases.
// ---------------------------------------------------------------------------
#define ROWB     144
#define TILE_B   (128 * ROWB)          // 18432
#define STAGE    (2 * TILE_B)          // 36864
#define NSTAGES  3
#define SMEMG    (NSTAGES * STAGE)     // 110592

template <bool MASK>
__global__ __launch_bounds__(128, 2) void gemm_f16(
    const __half* __restrict__ A, const __half* __restrict__ B, int Kdim,
    const int* __restrict__ mask, const float* __restrict__ invp,
    void* __restrict__ outp, int out_ld)
{
    extern __shared__ char smem[];
    const uint32_t sbase = smem_to_u32(smem);
    const int tid  = threadIdx.x;
    const int warp = tid >> 5;
    const int lane = tid & 31;
    const int bm = blockIdx.y * 128;
    const int bn = blockIdx.x * 128;
    const int wm = (warp & 1) * 64;
    const int wn = (warp >> 1) * 64;

    // ldmatrix per-thread address components
    const int a_row = wm + (lane & 15);
    const int a_kh  = (lane >> 4) * 16;
    const int b_row = wn + ((lane >> 4) << 3) + (lane & 7);
    const int b_kh  = ((lane >> 3) & 1) * 16;

    float acc[4][8][4];
    #pragma unroll
    for (int mt = 0; mt < 4; mt++)
        #pragma unroll
        for (int nt = 0; nt < 8; nt++)
            #pragma unroll
            for (int r = 0; r < 4; r++) acc[mt][nt][r] = 0.0f;

    // One BK=64 chunk: 2 tiles of 128 rows x 128 bytes
    #define ISSUEG(cc, buf) do { \
        const int k0_ = (cc) << 6; \
        _Pragma("unroll") \
        for (int p = 0; p < 8; p++) { \
            const int v_   = tid + p * 128; \
            const int row_ = v_ >> 3; \
            const int c16_ = v_ & 7; \
            const uint32_t dst_ = sbase + (buf) * STAGE \
                                + row_ * ROWB + c16_ * 16; \
            const size_t ga_ = (size_t)(bm + row_) * Kdim + k0_ + c16_ * 8; \
            const size_t gb_ = (size_t)(bn + row_) * Kdim + k0_ + c16_ * 8; \
            CP16(dst_ + 0 * TILE_B, A + ga_); \
            CP16(dst_ + 1 * TILE_B, B + gb_); \
        } \
        CP_COMMIT(); \
    } while (0)

    ISSUEG(0, 0);
    ISSUEG(1, 1);

    const int NC = Kdim >> 6;
    int buf = 0;
    for (int c = 0; c < NC; c++) {
        CP_WAIT1();          // chunk c resident (<=1 younger group pending)
        __syncthreads();     // all warps past compute of chunk c-1
        if (c + 2 < NC) {
            int nb = buf + 2; if (nb >= NSTAGES) nb -= NSTAGES;
            ISSUEG(c + 2, nb);
        }

        const uint32_t sA = sbase + buf * STAGE;
        const uint32_t sB = sA + TILE_B;

        #pragma unroll
        for (int ks = 0; ks < 4; ks++) {
            const uint32_t kb0 = ks * 32;

            uint32_t a[4][4], b[8][2];
            #pragma unroll
            for (int mt = 0; mt < 4; mt++) {
                const uint32_t ad = sA + (a_row + mt * 16) * ROWB + a_kh + kb0;
                LDSM4(a[mt][0], a[mt][1], a[mt][2], a[mt][3], ad);
            }
            #pragma unroll
            for (int p = 0; p < 4; p++) {
                const uint32_t bd = sB + (b_row + p * 16) * ROWB + b_kh + kb0;
                LDSM4(b[2 * p][0], b[2 * p][1], b[2 * p + 1][0], b[2 * p + 1][1], bd);
            }
            #pragma unroll
            for (int nt = 0; nt < 8; nt++)
                #pragma unroll
                for (int mt = 0; mt < 4; mt++)
                    mma16816_f16(acc[mt][nt], a[mt], b[nt]);
        }
        if (++buf >= NSTAGES) buf = 0;
    }
    #undef ISSUEG

    // Epilogue
    const int lr = lane >> 2;
    #pragma unroll
    for (int mt = 0; mt < 4; mt++) {
        #pragma unroll
        for (int half = 0; half < 2; half++) {
            const int rloc = bm + wm + mt * 16 + lr + half * 8;
            float inv = 1.0f;
            if (!MASK) inv = invp[rloc];
            const size_t rg = (size_t)rloc;
            #pragma unroll
            for (int nt = 0; nt < 8; nt++) {
                const size_t o = rg * (size_t)out_ld
                               + (bn + wn + nt * 8 + (lane & 3) * 2);
                if (MASK) {
                    int2 mv = *reinterpret_cast<const int2*>(mask + o);
                    float2 v;
                    v.x = mv.x ? acc[mt][nt][half * 2 + 0] * LOG2E : NEG_H;
                    v.y = mv.y ? acc[mt][nt][half * 2 + 1] * LOG2E : NEG_H;
                    *reinterpret_cast<__half2*>((__half*)outp + o) =
                        __float22half2_rn(v);
                } else {
                    float2 v;
                    v.x = acc[mt][nt][half * 2 + 0] * inv;
                    v.y = acc[mt][nt][half * 2 + 1] * inv;
                    *reinterpret_cast<float2*>((float*)outp + o) = v;
                }
            }
        }
    }
}

// ---------------------------------------------------------------------------
// Fused softmax over fp16 log2-scaled scores.
// Pass 1: plain max (cheap). Pass 2: w = 2^(s - max), sum, fp16 weights,
// and collect argmax candidates (s >= rmax - DELTA) into g_cand.
// ---------------------------------------------------------------------------
__global__ __launch_bounds__(256) void softmax_kernel(
    const __half* __restrict__ S, __half* __restrict__ Wf,
    float* __restrict__ invp, int* __restrict__ cand)
{
    const int row = blockIdx.x;
    const __half* s = S + (size_t)row * N_ATOMS;
    const int tid = threadIdx.x;

    __shared__ float sred[256];
    __shared__ int   scand[MAXCAND];
    __shared__ int   scount;

    if (tid == 0) scount = 0;

    // Pass 1: max
    float vmax = -INFINITY;
    for (int c0 = tid * 8; c0 < N_ATOMS; c0 += 2048) {
        uint4 u = *reinterpret_cast<const uint4*>(s + c0);
        float2 f0 = __half22float2(*reinterpret_cast<__half2*>(&u.x));
        float2 f1 = __half22float2(*reinterpret_cast<__half2*>(&u.y));
        float2 f2 = __half22float2(*reinterpret_cast<__half2*>(&u.z));
        float2 f3 = __half22float2(*reinterpret_cast<__half2*>(&u.w));
        vmax = fmaxf(vmax, fmaxf(fmaxf(f0.x, f0.y), fmaxf(f1.x, f1.y)));
        vmax = fmaxf(vmax, fmaxf(fmaxf(f2.x, f2.y), fmaxf(f3.x, f3.y)));
    }
    sred[tid] = vmax;
    __syncthreads();
    for (int off = 128; off > 0; off >>= 1) {
        if (tid < off) sred[tid] = fmaxf(sred[tid], sred[tid + off]);
        __syncthreads();
    }
    const float rmax = sred[0];
    const float thresh = rmax - DELTA;
    __syncthreads();

    // Pass 2: exp, sum, weights, candidate collection
    __half* wf = Wf + (size_t)row * N_ATOMS;
    float lsum = 0.0f;
    for (int c0 = tid * 8; c0 < N_ATOMS; c0 += 2048) {
        uint4 u = *reinterpret_cast<const uint4*>(s + c0);
        float f[8];
        float2 t2;
        t2 = __half22float2(*reinterpret_cast<__half2*>(&u.x)); f[0]=t2.x; f[1]=t2.y;
        t2 = __half22float2(*reinterpret_cast<__half2*>(&u.y)); f[2]=t2.x; f[3]=t2.y;
        t2 = __half22float2(*reinterpret_cast<__half2*>(&u.z)); f[4]=t2.x; f[5]=t2.y;
        t2 = __half22float2(*reinterpret_cast<__half2*>(&u.w)); f[6]=t2.x; f[7]=t2.y;
        float w[8];
        #pragma unroll
        for (int j = 0; j < 8; j++) {
            w[j] = ex2f(f[j] - rmax);
            if (f[j] >= thresh) {
                int slot = atomicAdd(&scount, 1);
                if (slot < MAXCAND) scand[slot] = c0 + j;
            }
        }
        lsum += ((w[0] + w[1]) + (w[2] + w[3])) + ((w[4] + w[5]) + (w[6] + w[7]));
        uint4 o;
        *reinterpret_cast<__half2*>(&o.x) = __float22half2_rn(make_float2(w[0], w[1]));
        *reinterpret_cast<__half2*>(&o.y) = __float22half2_rn(make_float2(w[2], w[3]));
        *reinterpret_cast<__half2*>(&o.z) = __float22half2_rn(make_float2(w[4], w[5]));
        *reinterpret_cast<__half2*>(&o.w) = __float22half2_rn(make_float2(w[6], w[7]));
        *reinterpret_cast<uint4*>(wf + c0) = o;
    }
    sred[tid] = lsum;
    __syncthreads();
    for (int off = 128; off > 0; off >>= 1) {
        if (tid < off) sred[tid] += sred[tid + off];
        __syncthreads();
    }
    if (tid == 0) {
        invp[row] = 1.0f / sred[0];
        int cnt = scount; if (cnt > MAXCAND) cnt = MAXCAND;
        cand[row * (MAXCAND + 1)] = cnt;
    }
    __syncthreads();
    if (tid < MAXCAND && tid < scount)
        cand[row * (MAXCAND + 1) + 1 + tid] = scand[tid];
}

// ---------------------------------------------------------------------------
// Exact fp32 argmax rescue over collected candidates. One warp per row.
// ---------------------------------------------------------------------------
#define BETTER(v, i, V, I) ((v) > (V) || ((v) == (V) && (i) < (I)))

__global__ __launch_bounds__(256) void argmax_rescue_kernel(
    const float* __restrict__ X, const float* __restrict__ Dict,
    const int* __restrict__ cand, float* __restrict__ argmax_out)
{
    const int row = blockIdx.x * 8 + (threadIdx.x >> 5);
    const int lid = threadIdx.x & 31;
    const int* crow = cand + row * (MAXCAND + 1);
    const int cnt = crow[0];

    const float* x = X + (size_t)row * DM;
    float bv = -INFINITY; int bi = 0x7fffffff;
    for (int j = 0; j < cnt; j++) {
        const int ci = crow[1 + j];
        const float* d = Dict + (size_t)ci * DM;
        float sc = 0.0f;
        for (int k = lid * 4; k < DM; k += 128) {
            float4 xv = *reinterpret_cast<const float4*>(x + k);
            float4 dv = *reinterpret_cast<const float4*>(d + k);
            sc += xv.x * dv.x + xv.y * dv.y + xv.z * dv.z + xv.w * dv.w;
        }
        #pragma unroll
        for (int off = 16; off > 0; off >>= 1)
            sc += __shfl_xor_sync(0xffffffffu, sc, off);
        if (BETTER(sc, ci, bv, bi)) { bv = sc; bi = ci; }
    }
    if (lid == 0) argmax_out[row] = (float)bi;
}

// ---------------------------------------------------------------------------
// Launch
// ---------------------------------------------------------------------------
extern "C" void kernel_launch(void* const* d_in, const int* in_sizes, int n_in,
                              void* d_out, int out_size)
{
    const float* X    = (const float*)d_in[0];
    const float* Dict = (const float*)d_in[1];
    const int*   mask = (const int*)d_in[2];
    float* out = (float*)d_out;

    __half *scores, *Xf, *Df, *DTf, *Wf;
    cudaGetSymbolAddress((void**)&scores, g_scores);
    cudaGetSymbolAddress((void**)&Xf, g_Xf);
    cudaGetSymbolAddress((void**)&Df, g_Df);
    cudaGetSymbolAddress((void**)&DTf, g_DTf);
    cudaGetSymbolAddress((void**)&Wf, g_Wf);
    float* invp; cudaGetSymbolAddress((void**)&invp, g_inv);
    int* cand; cudaGetSymbolAddress((void**)&cand, g_cand);

    float* recon_out  = out;
    float* argmax_out = out + (size_t)M_ROWS * DM;

    static bool attr_set = false;
    if (!attr_set) {
        cudaFuncSetAttribute(gemm_f16<true>,
                             cudaFuncAttributeMaxDynamicSharedMemorySize, SMEMG);
        cudaFuncSetAttribute(gemm_f16<false>,
                             cudaFuncAttributeMaxDynamicSharedMemorySize, SMEMG);
        attr_set = true;
    }

    // 1) fp16 conversions: X, dict (K-major), dict^T
    {
        int n4x = (M_ROWS * DM) / 4;
        to_f16_kernel<<<(n4x + 255) / 256, 256>>>(X, Xf, n4x);
        int n4d = (N_ATOMS * DM) / 4;
        to_f16_kernel<<<(n4d + 255) / 256, 256>>>(Dict, Df, n4d);
        dim3 grid(DM / 32, N_ATOMS / 32), blk(32, 8);
        transpose_f16_kernel<<<grid, blk>>>(Dict, DTf);
    }

    // 2) scores*log2e (fp16) = (Xf · Df^T)*log2e with fused mask
    {
        dim3 grid(N_ATOMS / 128, M_ROWS / 128);
        gemm_f16<true><<<grid, 128, SMEMG>>>(
            Xf, Df, DM, mask, nullptr, scores, N_ATOMS);
    }

    // 3) fused softmax: max, exp via MUFU, weights + inv + candidates
    softmax_kernel<<<M_ROWS, 256>>>(scores, Wf, invp, cand);

    // 4) exact fp32 argmax among collected candidates
    argmax_rescue_kernel<<<M_ROWS / 8, 256>>>(X, Dict, cand, argmax_out);

    // 5) reconstruction = (Wf · DTf) * inv[row]
    {
        dim3 grid(DM / 128, M_ROWS / 128);
        gemm_f16<false><<<grid, 128, SMEMG>>>(
            Wf, DTf, N_ATOMS, nullptr, invp, recon_out, DM);
    }
}

// round 12
// speedup vs baseline: 1.3606x; 1.0407x over previous
#include <cuda_runtime.h>
#include <cuda_fp16.h>
#include <math.h>
#include <stdint.h>

// ---------------------------------------------------------------------------
// Problem dims
// ---------------------------------------------------------------------------
#define M_ROWS  8192      // 4 * 2048
#define N_ATOMS 16384
#define DM      1024
#define LOG2E   1.4426950408889634f
#define CANDF   0.99448f  // 2^-0.008 — candidate threshold factor on w
#define MAXCAND 16

// ---------------------------------------------------------------------------
// Scratch (__device__ globals; allocation APIs are forbidden)
// ---------------------------------------------------------------------------
__device__ __half  g_Xf[(size_t)M_ROWS * DM];
__device__ __half  g_Df[(size_t)N_ATOMS * DM];             // dict fp16 K-major
__device__ __half  g_DTf[(size_t)DM * N_ATOMS];            // dict^T fp16
__device__ __half  g_Wf[(size_t)M_ROWS * N_ATOMS];         // 256 MB fp16 weights
__device__ float   g_inv[M_ROWS];

// ---------------------------------------------------------------------------
// Low-level helpers (sm_80+ baseline PTX only — NO tcgen05 on plain sm_103)
// ---------------------------------------------------------------------------
__device__ __forceinline__ uint32_t smem_to_u32(const void* p) {
    uint32_t a;
    asm("{ .reg .u64 t; cvta.to.shared.u64 t, %1; cvt.u32.u64 %0, t; }"
        : "=r"(a) : "l"(p));
    return a;
}

#define CP16(dst, src) \
    asm volatile("cp.async.cg.shared.global [%0], [%1], 16;" \
                 :: "r"(dst), "l"(src) : "memory")
#define CP_COMMIT() asm volatile("cp.async.commit_group;" ::: "memory")
#define CP_WAIT2()  asm volatile("cp.async.wait_group 2;"  ::: "memory")

#define LDSM4(r0, r1, r2, r3, addr) \
    asm volatile("ldmatrix.sync.aligned.m8n8.x4.shared.b16 {%0,%1,%2,%3}, [%4];" \
        : "=r"(r0), "=r"(r1), "=r"(r2), "=r"(r3) : "r"(addr))

__device__ __forceinline__ void mma16816_f16(float* c, const uint32_t* a,
                                             const uint32_t* b) {
    asm volatile(
        "mma.sync.aligned.m16n8k16.row.col.f32.f16.f16.f32 "
        "{%0,%1,%2,%3}, {%4,%5,%6,%7}, {%8,%9}, {%0,%1,%2,%3};"
        : "+f"(c[0]), "+f"(c[1]), "+f"(c[2]), "+f"(c[3])
        : "r"(a[0]), "r"(a[1]), "r"(a[2]), "r"(a[3]), "r"(b[0]), "r"(b[1]));
}

__device__ __forceinline__ float ex2f(float x) {
    float y;
    asm("ex2.approx.ftz.f32 %0, %1;" : "=f"(y) : "f"(x));
    return y;
}

// ---------------------------------------------------------------------------
// Conversion kernels
// ---------------------------------------------------------------------------
__global__ __launch_bounds__(256) void to_f16_kernel(
    const float* __restrict__ src, __half* __restrict__ dst, int n4)
{
    int i = blockIdx.x * blockDim.x + threadIdx.x;
    if (i >= n4) return;
    float4 v = reinterpret_cast<const float4*>(src)[i];
    ushort4 hv;
    hv.x = __half_as_ushort(__float2half_rn(v.x));
    hv.y = __half_as_ushort(__float2half_rn(v.y));
    hv.z = __half_as_ushort(__float2half_rn(v.z));
    hv.w = __half_as_ushort(__float2half_rn(v.w));
    reinterpret_cast<ushort4*>(dst)[i] = hv;
}

// dict [N_ATOMS][DM] fp32 -> DTf [DM][N_ATOMS] fp16
__global__ __launch_bounds__(256) void transpose_f16_kernel(
    const float* __restrict__ dict, __half* __restrict__ DTf)
{
    __shared__ float t[32][33];
    const int bx = blockIdx.x;
    const int by = blockIdx.y;
    const int tx = threadIdx.x;
    const int ty = threadIdx.y;
    #pragma unroll
    for (int k = 0; k < 32; k += 8)
        t[ty + k][tx] = dict[(size_t)(by * 32 + ty + k) * DM + bx * 32 + tx];
    __syncthreads();
    #pragma unroll
    for (int k = 0; k < 32; k += 8) {
        size_t o = (size_t)(bx * 32 + ty + k) * N_ATOMS + by * 32 + tx;
        DTf[o] = __float2half_rn(t[tx][ty + k]);
    }
}

// ---------------------------------------------------------------------------
// Unified 1-term fp16 GEMM via ldmatrix + mma.sync, BK=32, 4-stage cp.async.
// out tile 128x128 = A[M,K] · B[N,K]^T
// MASK=true : out is __half WEIGHT w = 2^(s*log2e), masked -> 0  (scores+exp)
// MASK=false: out is float, row scaled by invp[row] (recon)
// 128 threads = 4 warps (2x2) of 64x64.
// smem rows: 64B data + 16B pad (80B) — conflict-free LDSM phases.
// ---------------------------------------------------------------------------
#define ROWB     80
#define TILE_B   (128 * ROWB)          // 10240
#define STAGE    (2 * TILE_B)          // 20480
#define NSTAGES  4
#define SMEMG    (NSTAGES * STAGE)     // 81920

template <bool MASK>
__global__ __launch_bounds__(128, 2) void gemm_f16(
    const __half* __restrict__ A, const __half* __restrict__ B, int Kdim,
    const int* __restrict__ mask, const float* __restrict__ invp,
    void* __restrict__ outp, int out_ld)
{
    extern __shared__ char smem[];
    const uint32_t sbase = smem_to_u32(smem);
    const int tid  = threadIdx.x;
    const int warp = tid >> 5;
    const int lane = tid & 31;
    const int bm = blockIdx.y * 128;
    const int bn = blockIdx.x * 128;
    const int wm = (warp & 1) * 64;
    const int wn = (warp >> 1) * 64;

    // ldmatrix per-thread address components
    const int a_row = wm + (lane & 15);
    const int a_kh  = (lane >> 4) * 16;
    const int b_row = wn + ((lane >> 4) << 3) + (lane & 7);
    const int b_kh  = ((lane >> 3) & 1) * 16;

    float acc[4][8][4];
    #pragma unroll
    for (int mt = 0; mt < 4; mt++)
        #pragma unroll
        for (int nt = 0; nt < 8; nt++)
            #pragma unroll
            for (int r = 0; r < 4; r++) acc[mt][nt][r] = 0.0f;

    #define ISSUEG(cc, buf) do { \
        const int k0_ = (cc) << 5; \
        _Pragma("unroll") \
        for (int p = 0; p < 4; p++) { \
            const int v_   = tid + p * 128; \
            const int row_ = v_ >> 2; \
            const int c16_ = v_ & 3; \
            const uint32_t dst_ = sbase + (buf) * STAGE \
                                + row_ * ROWB + c16_ * 16; \
            const size_t ga_ = (size_t)(bm + row_) * Kdim + k0_ + c16_ * 8; \
            const size_t gb_ = (size_t)(bn + row_) * Kdim + k0_ + c16_ * 8; \
            CP16(dst_ + 0 * TILE_B, A + ga_); \
            CP16(dst_ + 1 * TILE_B, B + gb_); \
        } \
        CP_COMMIT(); \
    } while (0)

    ISSUEG(0, 0);
    ISSUEG(1, 1);
    ISSUEG(2, 2);

    const int NC = Kdim >> 5;
    for (int c = 0; c < NC; c++) {
        CP_WAIT2();          // chunk c resident (<=2 younger groups pending)
        __syncthreads();     // all warps past compute of chunk c-1
        if (c + 3 < NC) ISSUEG(c + 3, (c + 3) & 3);

        const uint32_t sA = sbase + (c & 3) * STAGE;
        const uint32_t sB = sA + TILE_B;

        #pragma unroll
        for (int ks = 0; ks < 2; ks++) {
            const uint32_t kb0 = ks * 32;

            uint32_t a[4][4], b[8][2];
            #pragma unroll
            for (int mt = 0; mt < 4; mt++) {
                const uint32_t ad = sA + (a_row + mt * 16) * ROWB + a_kh + kb0;
                LDSM4(a[mt][0], a[mt][1], a[mt][2], a[mt][3], ad);
            }
            #pragma unroll
            for (int p = 0; p < 4; p++) {
                const uint32_t bd = sB + (b_row + p * 16) * ROWB + b_kh + kb0;
                LDSM4(b[2 * p][0], b[2 * p][1], b[2 * p + 1][0], b[2 * p + 1][1], bd);
            }
            #pragma unroll
            for (int nt = 0; nt < 8; nt++)
                #pragma unroll
                for (int mt = 0; mt < 4; mt++)
                    mma16816_f16(acc[mt][nt], a[mt], b[nt]);
        }
    }
    #undef ISSUEG

    // Epilogue
    const int lr = lane >> 2;
    #pragma unroll
    for (int mt = 0; mt < 4; mt++) {
        #pragma unroll
        for (int half = 0; half < 2; half++) {
            const int rloc = bm + wm + mt * 16 + lr + half * 8;
            float inv = 1.0f;
            if (!MASK) inv = invp[rloc];
            const size_t rg = (size_t)rloc;
            #pragma unroll
            for (int nt = 0; nt < 8; nt++) {
                const size_t o = rg * (size_t)out_ld
                               + (bn + wn + nt * 8 + (lane & 3) * 2);
                if (MASK) {
                    // fused softmax numerator: w = 2^(s*log2e), masked -> 0
                    int2 mv = *reinterpret_cast<const int2*>(mask + o);
                    float2 v;
                    v.x = mv.x ? ex2f(acc[mt][nt][half * 2 + 0] * LOG2E) : 0.0f;
                    v.y = mv.y ? ex2f(acc[mt][nt][half * 2 + 1] * LOG2E) : 0.0f;
                    *reinterpret_cast<__half2*>((__half*)outp + o) =
                        __float22half2_rn(v);
                } else {
                    float2 v;
                    v.x = acc[mt][nt][half * 2 + 0] * inv;
                    v.y = acc[mt][nt][half * 2 + 1] * inv;
                    *reinterpret_cast<float2*>((float*)outp + o) = v;
                }
            }
        }
    }
}

// ---------------------------------------------------------------------------
// Fused softmax-denominator + exact argmax, one block (256 thr) per row.
// Pass 1: sum + max over fp16 weights. Pass 2 (L2-hot re-read): collect
// candidates w >= wmax*CANDF. Then exact fp32 dot per candidate (block-wide
// over DM=1024 = 256 thr x 4), pick winner (value, then smaller index).
// ---------------------------------------------------------------------------
#define BETTER(v, i, V, I) ((v) > (V) || ((v) == (V) && (i) < (I)))

__global__ __launch_bounds__(256) void softmax_rescue_kernel(
    const __half* __restrict__ Wf, const float* __restrict__ X,
    const float* __restrict__ Dict, float* __restrict__ invp,
    float* __restrict__ argmax_out)
{
    const int row = blockIdx.x;
    const __half* wf = Wf + (size_t)row * N_ATOMS;
    const int tid = threadIdx.x;

    __shared__ float ssum[256];
    __shared__ float smax[256];
    __shared__ float sdot[256];
    __shared__ int   scand[MAXCAND];
    __shared__ int   scount;

    if (tid == 0) scount = 0;

    // Pass 1: sum + max
    float lsum = 0.0f, lmax = -INFINITY;
    for (int c0 = tid * 8; c0 < N_ATOMS; c0 += 2048) {
        uint4 u = *reinterpret_cast<const uint4*>(wf + c0);
        float2 f0 = __half22float2(*reinterpret_cast<__half2*>(&u.x));
        float2 f1 = __half22float2(*reinterpret_cast<__half2*>(&u.y));
        float2 f2 = __half22float2(*reinterpret_cast<__half2*>(&u.z));
        float2 f3 = __half22float2(*reinterpret_cast<__half2*>(&u.w));
        lsum += ((f0.x + f0.y) + (f1.x + f1.y))
              + ((f2.x + f2.y) + (f3.x + f3.y));
        lmax = fmaxf(lmax, fmaxf(fmaxf(f0.x, f0.y), fmaxf(f1.x, f1.y)));
        lmax = fmaxf(lmax, fmaxf(fmaxf(f2.x, f2.y), fmaxf(f3.x, f3.y)));
    }
    ssum[tid] = lsum; smax[tid] = lmax;
    __syncthreads();
    for (int off = 128; off > 0; off >>= 1) {
        if (tid < off) {
            ssum[tid] += ssum[tid + off];
            smax[tid] = fmaxf(smax[tid], smax[tid + off]);
        }
        __syncthreads();
    }
    const float thresh = smax[0] * CANDF;
    __syncthreads();

    // Pass 2: candidate collection (row is L2-hot)
    for (int c0 = tid * 8; c0 < N_ATOMS; c0 += 2048) {
        uint4 u = *reinterpret_cast<const uint4*>(wf + c0);
        float f[8];
        float2 t2;
        t2 = __half22float2(*reinterpret_cast<__half2*>(&u.x)); f[0]=t2.x; f[1]=t2.y;
        t2 = __half22float2(*reinterpret_cast<__half2*>(&u.y)); f[2]=t2.x; f[3]=t2.y;
        t2 = __half22float2(*reinterpret_cast<__half2*>(&u.z)); f[4]=t2.x; f[5]=t2.y;
        t2 = __half22float2(*reinterpret_cast<__half2*>(&u.w)); f[6]=t2.x; f[7]=t2.y;
        #pragma unroll
        for (int j = 0; j < 8; j++) {
            if (f[j] >= thresh) {
                int slot = atomicAdd(&scount, 1);
                if (slot < MAXCAND) scand[slot] = c0 + j;
            }
        }
    }
    __syncthreads();
    int cnt = scount; if (cnt > MAXCAND) cnt = MAXCAND;

    // Exact fp32 dot per candidate; block-wide over DM (256 thr x 4 = 1024)
    const float* x = X + (size_t)row * DM;
    float4 xv = *reinterpret_cast<const float4*>(x + tid * 4);
    float bv = -INFINITY; int bi = 0x7fffffff;
    for (int j = 0; j < cnt; j++) {
        const int ci = scand[j];
        float4 dv = *reinterpret_cast<const float4*>(
            Dict + (size_t)ci * DM + tid * 4);
        sdot[tid] = xv.x * dv.x + xv.y * dv.y + xv.z * dv.z + xv.w * dv.w;
        __syncthreads();
        for (int off = 128; off > 0; off >>= 1) {
            if (tid < off) sdot[tid] += sdot[tid + off];
            __syncthreads();
        }
        const float sc = sdot[0];
        if (BETTER(sc, ci, bv, bi)) { bv = sc; bi = ci; }
        __syncthreads();
    }
    if (tid == 0) {
        argmax_out[row] = (float)bi;
        invp[row] = 1.0f / ssum[0];
    }
}

// ---------------------------------------------------------------------------
// Launch
// ---------------------------------------------------------------------------
extern "C" void kernel_launch(void* const* d_in, const int* in_sizes, int n_in,
                              void* d_out, int out_size)
{
    const float* X    = (const float*)d_in[0];
    const float* Dict = (const float*)d_in[1];
    const int*   mask = (const int*)d_in[2];
    float* out = (float*)d_out;

    __half *Xf, *Df, *DTf, *Wf;
    cudaGetSymbolAddress((void**)&Xf, g_Xf);
    cudaGetSymbolAddress((void**)&Df, g_Df);
    cudaGetSymbolAddress((void**)&DTf, g_DTf);
    cudaGetSymbolAddress((void**)&Wf, g_Wf);
    float* invp; cudaGetSymbolAddress((void**)&invp, g_inv);

    float* recon_out  = out;
    float* argmax_out = out + (size_t)M_ROWS * DM;

    static bool attr_set = false;
    if (!attr_set) {
        cudaFuncSetAttribute(gemm_f16<true>,
                             cudaFuncAttributeMaxDynamicSharedMemorySize, SMEMG);
        cudaFuncSetAttribute(gemm_f16<false>,
                             cudaFuncAttributeMaxDynamicSharedMemorySize, SMEMG);
        attr_set = true;
    }

    // 1) fp16 conversions: X, dict (K-major), dict^T
    {
        int n4x = (M_ROWS * DM) / 4;
        to_f16_kernel<<<(n4x + 255) / 256, 256>>>(X, Xf, n4x);
        int n4d = (N_ATOMS * DM) / 4;
        to_f16_kernel<<<(n4d + 255) / 256, 256>>>(Dict, Df, n4d);
        dim3 grid(DM / 32, N_ATOMS / 32), blk(32, 8);
        transpose_f16_kernel<<<grid, blk>>>(Dict, DTf);
    }

    // 2) fused scores+exp GEMM: Wf = 2^((Xf · Df^T)*log2e), masked -> 0
    {
        dim3 grid(N_ATOMS / 128, M_ROWS / 128);
        gemm_f16<true><<<grid, 128, SMEMG>>>(
            Xf, Df, DM, mask, nullptr, Wf, N_ATOMS);
    }

    // 3) fused softmax denominator + exact argmax
    softmax_rescue_kernel<<<M_ROWS, 256>>>(Wf, X, Dict, invp, argmax_out);

    // 4) reconstruction = (Wf · DTf) * inv[row]
    {
        dim3 grid(DM / 128, M_ROWS / 128);
        gemm_f16<false><<<grid, 128, SMEMG>>>(
            Wf, DTf, N_ATOMS, nullptr, invp, recon_out, DM);
    }
}

// round 13
// speedup vs baseline: 1.3759x; 1.0112x over previous
#include <cuda_runtime.h>
#include <cuda_fp16.h>
#include <math.h>
#include <stdint.h>

// ---------------------------------------------------------------------------
// Problem dims
// ---------------------------------------------------------------------------
#define M_ROWS  8192      // 4 * 2048
#define N_ATOMS 16384
#define DM      1024
#define LOG2E   1.4426950408889634f
#define CANDF   0.99448f  // 2^-0.008 — candidate threshold factor on w
#define MAXCAND 16

// ---------------------------------------------------------------------------
// Scratch (__device__ globals; allocation APIs are forbidden)
// ---------------------------------------------------------------------------
__device__ __half  g_Xf[(size_t)M_ROWS * DM];              // x * log2e, fp16
__device__ __half  g_Df[(size_t)N_ATOMS * DM];             // dict fp16 K-major
__device__ __half  g_DTf[(size_t)DM * N_ATOMS];            // dict^T fp16
__device__ __half  g_Wf[(size_t)M_ROWS * N_ATOMS];         // 256 MB fp16 weights
__device__ float   g_sum[M_ROWS];
__device__ unsigned g_max[M_ROWS];                         // float bits (w>=0)
__device__ float   g_inv[M_ROWS];

// ---------------------------------------------------------------------------
// Low-level helpers (sm_80+ baseline PTX only — NO tcgen05 on plain sm_103)
// ---------------------------------------------------------------------------
__device__ __forceinline__ uint32_t smem_to_u32(const void* p) {
    uint32_t a;
    asm("{ .reg .u64 t; cvta.to.shared.u64 t, %1; cvt.u32.u64 %0, t; }"
        : "=r"(a) : "l"(p));
    return a;
}

#define CP16(dst, src) \
    asm volatile("cp.async.cg.shared.global [%0], [%1], 16;" \
                 :: "r"(dst), "l"(src) : "memory")
#define CP_COMMIT() asm volatile("cp.async.commit_group;" ::: "memory")
#define CP_WAIT2()  asm volatile("cp.async.wait_group 2;"  ::: "memory")

#define LDSM4(r0, r1, r2, r3, addr) \
    asm volatile("ldmatrix.sync.aligned.m8n8.x4.shared.b16 {%0,%1,%2,%3}, [%4];" \
        : "=r"(r0), "=r"(r1), "=r"(r2), "=r"(r3) : "r"(addr))

__device__ __forceinline__ void mma16816_f16(float* c, const uint32_t* a,
                                             const uint32_t* b) {
    asm volatile(
        "mma.sync.aligned.m16n8k16.row.col.f32.f16.f16.f32 "
        "{%0,%1,%2,%3}, {%4,%5,%6,%7}, {%8,%9}, {%0,%1,%2,%3};"
        : "+f"(c[0]), "+f"(c[1]), "+f"(c[2]), "+f"(c[3])
        : "r"(a[0]), "r"(a[1]), "r"(a[2]), "r"(a[3]), "r"(b[0]), "r"(b[1]));
}

__device__ __forceinline__ float ex2f(float x) {
    float y;
    asm("ex2.approx.ftz.f32 %0, %1;" : "=f"(y) : "f"(x));
    return y;
}

// ---------------------------------------------------------------------------
// Init: zero per-row sum/max accumulators
// ---------------------------------------------------------------------------
__global__ __launch_bounds__(256) void init_kernel(
    float* __restrict__ sum, unsigned* __restrict__ mx)
{
    int i = blockIdx.x * blockDim.x + threadIdx.x;
    if (i < M_ROWS) { sum[i] = 0.0f; mx[i] = 0u; }
}

// ---------------------------------------------------------------------------
// Conversion kernels
// ---------------------------------------------------------------------------
__global__ __launch_bounds__(256) void to_f16_scaled_kernel(
    const float* __restrict__ src, __half* __restrict__ dst, float scale, int n4)
{
    int i = blockIdx.x * blockDim.x + threadIdx.x;
    if (i >= n4) return;
    float4 v = reinterpret_cast<const float4*>(src)[i];
    ushort4 hv;
    hv.x = __half_as_ushort(__float2half_rn(v.x * scale));
    hv.y = __half_as_ushort(__float2half_rn(v.y * scale));
    hv.z = __half_as_ushort(__float2half_rn(v.z * scale));
    hv.w = __half_as_ushort(__float2half_rn(v.w * scale));
    reinterpret_cast<ushort4*>(dst)[i] = hv;
}

// dict [N_ATOMS][DM] fp32 -> Df fp16 (same layout) + DTf fp16 (transposed).
// Single read of dict.
__global__ __launch_bounds__(256) void convert_dict_kernel(
    const float* __restrict__ dict, __half* __restrict__ Df,
    __half* __restrict__ DTf)
{
    __shared__ float t[32][33];
    const int bx = blockIdx.x;   // DM tile
    const int by = blockIdx.y;   // atom tile
    const int tx = threadIdx.x;
    const int ty = threadIdx.y;
    #pragma unroll
    for (int k = 0; k < 32; k += 8) {
        float v = dict[(size_t)(by * 32 + ty + k) * DM + bx * 32 + tx];
        t[ty + k][tx] = v;
        Df[(size_t)(by * 32 + ty + k) * DM + bx * 32 + tx] = __float2half_rn(v);
    }
    __syncthreads();
    #pragma unroll
    for (int k = 0; k < 32; k += 8) {
        size_t o = (size_t)(bx * 32 + ty + k) * N_ATOMS + by * 32 + tx;
        DTf[o] = __float2half_rn(t[tx][ty + k]);
    }
}

// ---------------------------------------------------------------------------
// Unified 1-term fp16 GEMM via ldmatrix + mma.sync, BK=32, 4-stage cp.async.
// out tile 128x128 = A[M,K] · B[N,K]^T
// MASK=true : out is __half WEIGHT w = 2^s (A pre-scaled by log2e), masked->0;
//             epilogue also accumulates per-row sum (atomicAdd) and max
//             (atomicMax on float bits) of the fp16-rounded weights.
// MASK=false: out is float, row scaled by invp[row] (recon)
// 128 threads = 4 warps (2x2) of 64x64.
// smem rows: 64B data + 16B pad (80B) — conflict-free LDSM phases.
// ---------------------------------------------------------------------------
#define ROWB     80
#define TILE_B   (128 * ROWB)          // 10240
#define STAGE    (2 * TILE_B)          // 20480
#define NSTAGES  4
#define SMEMG    (NSTAGES * STAGE)     // 81920

template <bool MASK>
__global__ __launch_bounds__(128, 2) void gemm_f16(
    const __half* __restrict__ A, const __half* __restrict__ B, int Kdim,
    const int* __restrict__ mask, const float* __restrict__ invp,
    float* __restrict__ rsum, unsigned* __restrict__ rmax,
    void* __restrict__ outp, int out_ld)
{
    extern __shared__ char smem[];
    const uint32_t sbase = smem_to_u32(smem);
    const int tid  = threadIdx.x;
    const int warp = tid >> 5;
    const int lane = tid & 31;
    const int bm = blockIdx.y * 128;
    const int bn = blockIdx.x * 128;
    const int wm = (warp & 1) * 64;
    const int wn = (warp >> 1) * 64;

    // ldmatrix per-thread address components
    const int a_row = wm + (lane & 15);
    const int a_kh  = (lane >> 4) * 16;
    const int b_row = wn + ((lane >> 4) << 3) + (lane & 7);
    const int b_kh  = ((lane >> 3) & 1) * 16;

    float acc[4][8][4];
    #pragma unroll
    for (int mt = 0; mt < 4; mt++)
        #pragma unroll
        for (int nt = 0; nt < 8; nt++)
            #pragma unroll
            for (int r = 0; r < 4; r++) acc[mt][nt][r] = 0.0f;

    #define ISSUEG(cc, buf) do { \
        const int k0_ = (cc) << 5; \
        _Pragma("unroll") \
        for (int p = 0; p < 4; p++) { \
            const int v_   = tid + p * 128; \
            const int row_ = v_ >> 2; \
            const int c16_ = v_ & 3; \
            const uint32_t dst_ = sbase + (buf) * STAGE \
                                + row_ * ROWB + c16_ * 16; \
            const size_t ga_ = (size_t)(bm + row_) * Kdim + k0_ + c16_ * 8; \
            const size_t gb_ = (size_t)(bn + row_) * Kdim + k0_ + c16_ * 8; \
            CP16(dst_ + 0 * TILE_B, A + ga_); \
            CP16(dst_ + 1 * TILE_B, B + gb_); \
        } \
        CP_COMMIT(); \
    } while (0)

    ISSUEG(0, 0);
    ISSUEG(1, 1);
    ISSUEG(2, 2);

    const int NC = Kdim >> 5;
    for (int c = 0; c < NC; c++) {
        CP_WAIT2();          // chunk c resident (<=2 younger groups pending)
        __syncthreads();     // all warps past compute of chunk c-1
        if (c + 3 < NC) ISSUEG(c + 3, (c + 3) & 3);

        const uint32_t sA = sbase + (c & 3) * STAGE;
        const uint32_t sB = sA + TILE_B;

        #pragma unroll
        for (int ks = 0; ks < 2; ks++) {
            const uint32_t kb0 = ks * 32;

            uint32_t a[4][4], b[8][2];
            #pragma unroll
            for (int mt = 0; mt < 4; mt++) {
                const uint32_t ad = sA + (a_row + mt * 16) * ROWB + a_kh + kb0;
                LDSM4(a[mt][0], a[mt][1], a[mt][2], a[mt][3], ad);
            }
            #pragma unroll
            for (int p = 0; p < 4; p++) {
                const uint32_t bd = sB + (b_row + p * 16) * ROWB + b_kh + kb0;
                LDSM4(b[2 * p][0], b[2 * p][1], b[2 * p + 1][0], b[2 * p + 1][1], bd);
            }
            #pragma unroll
            for (int nt = 0; nt < 8; nt++)
                #pragma unroll
                for (int mt = 0; mt < 4; mt++)
                    mma16816_f16(acc[mt][nt], a[mt], b[nt]);
        }
    }
    #undef ISSUEG

    // Epilogue
    const int lr = lane >> 2;
    #pragma unroll
    for (int mt = 0; mt < 4; mt++) {
        #pragma unroll
        for (int half = 0; half < 2; half++) {
            const int rloc = bm + wm + mt * 16 + lr + half * 8;
            float inv = 1.0f;
            if (!MASK) inv = invp[rloc];
            const size_t rg = (size_t)rloc;
            float rsum_l = 0.0f, rmax_l = 0.0f;
            #pragma unroll
            for (int nt = 0; nt < 8; nt++) {
                const size_t o = rg * (size_t)out_ld
                               + (bn + wn + nt * 8 + (lane & 3) * 2);
                if (MASK) {
                    // fused softmax numerator: w = 2^s (A pre-scaled), mask->0
                    int2 mv = *reinterpret_cast<const int2*>(mask + o);
                    float2 v;
                    v.x = mv.x ? ex2f(acc[mt][nt][half * 2 + 0]) : 0.0f;
                    v.y = mv.y ? ex2f(acc[mt][nt][half * 2 + 1]) : 0.0f;
                    __half2 h2 = __float22half2_rn(v);
                    *reinterpret_cast<__half2*>((__half*)outp + o) = h2;
                    // accumulate from the ROUNDED values (consistency)
                    float2 vr = __half22float2(h2);
                    rsum_l += vr.x + vr.y;
                    rmax_l = fmaxf(rmax_l, fmaxf(vr.x, vr.y));
                } else {
                    float2 v;
                    v.x = acc[mt][nt][half * 2 + 0] * inv;
                    v.y = acc[mt][nt][half * 2 + 1] * inv;
                    *reinterpret_cast<float2*>((float*)outp + o) = v;
                }
            }
            if (MASK) {
                // quad reduce (lanes with same lr hold same row)
                rsum_l += __shfl_xor_sync(0xffffffffu, rsum_l, 1);
                rsum_l += __shfl_xor_sync(0xffffffffu, rsum_l, 2);
                rmax_l = fmaxf(rmax_l, __shfl_xor_sync(0xffffffffu, rmax_l, 1));
                rmax_l = fmaxf(rmax_l, __shfl_xor_sync(0xffffffffu, rmax_l, 2));
                if ((lane & 3) == 0) {
                    atomicAdd(rsum + rloc, rsum_l);
                    atomicMax(rmax + rloc, __float_as_uint(rmax_l));
                }
            }
        }
    }
}

// ---------------------------------------------------------------------------
// Exact argmax, one block (256 thr) per row. Single pass over fp16 weights:
// collect candidates w >= wmax*CANDF (wmax from GEMM1 atomics). Then exact
// fp32 dot per candidate (block-wide over DM=1024 = 256 thr x 4); winner by
// (value, then smaller index). Also publishes invp = 1/sum.
// ---------------------------------------------------------------------------
#define BETTER(v, i, V, I) ((v) > (V) || ((v) == (V) && (i) < (I)))

__global__ __launch_bounds__(256) void argmax_rescue_kernel(
    const __half* __restrict__ Wf, const float* __restrict__ X,
    const float* __restrict__ Dict, const float* __restrict__ rsum,
    const unsigned* __restrict__ rmax, float* __restrict__ invp,
    float* __restrict__ argmax_out)
{
    const int row = blockIdx.x;
    const __half* wf = Wf + (size_t)row * N_ATOMS;
    const int tid = threadIdx.x;

    __shared__ float sdot[256];
    __shared__ int   scand[MAXCAND];
    __shared__ int   scount;

    if (tid == 0) scount = 0;
    __syncthreads();

    const float thresh = __uint_as_float(rmax[row]) * CANDF;

    // Single pass: candidate collection
    for (int c0 = tid * 8; c0 < N_ATOMS; c0 += 2048) {
        uint4 u = *reinterpret_cast<const uint4*>(wf + c0);
        float f[8];
        float2 t2;
        t2 = __half22float2(*reinterpret_cast<__half2*>(&u.x)); f[0]=t2.x; f[1]=t2.y;
        t2 = __half22float2(*reinterpret_cast<__half2*>(&u.y)); f[2]=t2.x; f[3]=t2.y;
        t2 = __half22float2(*reinterpret_cast<__half2*>(&u.z)); f[4]=t2.x; f[5]=t2.y;
        t2 = __half22float2(*reinterpret_cast<__half2*>(&u.w)); f[6]=t2.x; f[7]=t2.y;
        #pragma unroll
        for (int j = 0; j < 8; j++) {
            if (f[j] >= thresh) {
                int slot = atomicAdd(&scount, 1);
                if (slot < MAXCAND) scand[slot] = c0 + j;
            }
        }
    }
    __syncthreads();
    int cnt = scount; if (cnt > MAXCAND) cnt = MAXCAND;

    // Exact fp32 dot per candidate; block-wide over DM (256 thr x 4 = 1024)
    const float* x = X + (size_t)row * DM;
    float4 xv = *reinterpret_cast<const float4*>(x + tid * 4);
    float bv = -INFINITY; int bi = 0x7fffffff;
    for (int j = 0; j < cnt; j++) {
        const int ci = scand[j];
        float4 dv = *reinterpret_cast<const float4*>(
            Dict + (size_t)ci * DM + tid * 4);
        sdot[tid] = xv.x * dv.x + xv.y * dv.y + xv.z * dv.z + xv.w * dv.w;
        __syncthreads();
        for (int off = 128; off > 0; off >>= 1) {
            if (tid < off) sdot[tid] += sdot[tid + off];
            __syncthreads();
        }
        const float sc = sdot[0];
        if (BETTER(sc, ci, bv, bi)) { bv = sc; bi = ci; }
        __syncthreads();
    }
    if (tid == 0) {
        argmax_out[row] = (float)bi;
        invp[row] = 1.0f / rsum[row];
    }
}

// ---------------------------------------------------------------------------
// Launch
// ---------------------------------------------------------------------------
extern "C" void kernel_launch(void* const* d_in, const int* in_sizes, int n_in,
                              void* d_out, int out_size)
{
    const float* X    = (const float*)d_in[0];
    const float* Dict = (const float*)d_in[1];
    const int*   mask = (const int*)d_in[2];
    float* out = (float*)d_out;

    __half *Xf, *Df, *DTf, *Wf;
    cudaGetSymbolAddress((void**)&Xf, g_Xf);
    cudaGetSymbolAddress((void**)&Df, g_Df);
    cudaGetSymbolAddress((void**)&DTf, g_DTf);
    cudaGetSymbolAddress((void**)&Wf, g_Wf);
    float* rsum; cudaGetSymbolAddress((void**)&rsum, g_sum);
    unsigned* rmax; cudaGetSymbolAddress((void**)&rmax, g_max);
    float* invp; cudaGetSymbolAddress((void**)&invp, g_inv);

    float* recon_out  = out;
    float* argmax_out = out + (size_t)M_ROWS * DM;

    static bool attr_set = false;
    if (!attr_set) {
        cudaFuncSetAttribute(gemm_f16<true>,
                             cudaFuncAttributeMaxDynamicSharedMemorySize, SMEMG);
        cudaFuncSetAttribute(gemm_f16<false>,
                             cudaFuncAttributeMaxDynamicSharedMemorySize, SMEMG);
        attr_set = true;
    }

    // 0) zero per-row accumulators
    init_kernel<<<M_ROWS / 256, 256>>>(rsum, rmax);

    // 1) fp16 conversions: X*log2e, dict (K-major + transposed, single read)
    {
        int n4x = (M_ROWS * DM) / 4;
        to_f16_scaled_kernel<<<(n4x + 255) / 256, 256>>>(X, Xf, LOG2E, n4x);
        dim3 grid(DM / 32, N_ATOMS / 32), blk(32, 8);
        convert_dict_kernel<<<grid, blk>>>(Dict, Df, DTf);
    }

    // 2) fused scores+exp GEMM: Wf = 2^(Xf · Df^T), masked -> 0,
    //    with per-row sum/max atomics
    {
        dim3 grid(N_ATOMS / 128, M_ROWS / 128);
        gemm_f16<true><<<grid, 128, SMEMG>>>(
            Xf, Df, DM, mask, nullptr, rsum, rmax, Wf, N_ATOMS);
    }

    // 3) exact argmax (single Wf pass) + invp
    argmax_rescue_kernel<<<M_ROWS, 256>>>(
        Wf, X, Dict, rsum, rmax, invp, argmax_out);

    // 4) reconstruction = (Wf · DTf) * inv[row]
    {
        dim3 grid(DM / 128, M_ROWS / 128);
        gemm_f16<false><<<grid, 128, SMEMG>>>(
            Wf, DTf, N_ATOMS, nullptr, invp, nullptr, nullptr, recon_out, DM);
    }
}

// round 14
// speedup vs baseline: 1.4126x; 1.0267x over previous
#include <cuda_runtime.h>
#include <cuda_fp16.h>
#include <math.h>
#include <stdint.h>

// ---------------------------------------------------------------------------
// Problem dims
// ---------------------------------------------------------------------------
#define M_ROWS  8192      // 4 * 2048
#define N_ATOMS 16384
#define DM      1024
#define LOG2E   1.4426950408889634f
#define CANDF   0.99448f  // 2^-0.008 — candidate threshold factor on w
#define MAXCAND 16
#define NTILES  (N_ATOMS / 128)   // 128 n-tiles per row
#define KSPLIT  4                 // split-K factor for recon GEMM

// ---------------------------------------------------------------------------
// Scratch (__device__ globals; allocation APIs are forbidden)
// ---------------------------------------------------------------------------
__device__ __half   g_Xf[(size_t)M_ROWS * DM];             // x * log2e, fp16
__device__ __half   g_Df[(size_t)N_ATOMS * DM];            // dict fp16 K-major
__device__ __half   g_DTf[(size_t)DM * N_ATOMS];           // dict^T fp16
__device__ __half   g_Wf[(size_t)M_ROWS * N_ATOMS];        // 256 MB fp16 weights
__device__ float    g_sum[M_ROWS];
__device__ unsigned g_tmax[(size_t)M_ROWS * NTILES];       // per-tile max bits
__device__ float    g_inv[M_ROWS];

// ---------------------------------------------------------------------------
// Low-level helpers (sm_80+ baseline PTX only — NO tcgen05 on plain sm_103)
// ---------------------------------------------------------------------------
__device__ __forceinline__ uint32_t smem_to_u32(const void* p) {
    uint32_t a;
    asm("{ .reg .u64 t; cvta.to.shared.u64 t, %1; cvt.u32.u64 %0, t; }"
        : "=r"(a) : "l"(p));
    return a;
}

#define CP16(dst, src) \
    asm volatile("cp.async.cg.shared.global [%0], [%1], 16;" \
                 :: "r"(dst), "l"(src) : "memory")
#define CP_COMMIT() asm volatile("cp.async.commit_group;" ::: "memory")
#define CP_WAIT2()  asm volatile("cp.async.wait_group 2;"  ::: "memory")

#define LDSM4(r0, r1, r2, r3, addr) \
    asm volatile("ldmatrix.sync.aligned.m8n8.x4.shared.b16 {%0,%1,%2,%3}, [%4];" \
        : "=r"(r0), "=r"(r1), "=r"(r2), "=r"(r3) : "r"(addr))

__device__ __forceinline__ void mma16816_f16(float* c, const uint32_t* a,
                                             const uint32_t* b) {
    asm volatile(
        "mma.sync.aligned.m16n8k16.row.col.f32.f16.f16.f32 "
        "{%0,%1,%2,%3}, {%4,%5,%6,%7}, {%8,%9}, {%0,%1,%2,%3};"
        : "+f"(c[0]), "+f"(c[1]), "+f"(c[2]), "+f"(c[3])
        : "r"(a[0]), "r"(a[1]), "r"(a[2]), "r"(a[3]), "r"(b[0]), "r"(b[1]));
}

__device__ __forceinline__ float ex2f(float x) {
    float y;
    asm("ex2.approx.ftz.f32 %0, %1;" : "=f"(y) : "f"(x));
    return y;
}

// ---------------------------------------------------------------------------
// Init: zero per-row sums, per-tile maxima, and the recon output (split-K
// accumulates into it with atomics).
// ---------------------------------------------------------------------------
__global__ __launch_bounds__(256) void init_kernel(
    float* __restrict__ sum, unsigned* __restrict__ tmax,
    float* __restrict__ recon)
{
    int i = blockIdx.x * blockDim.x + threadIdx.x;
    if (i < M_ROWS) sum[i] = 0.0f;
    int total_tm = M_ROWS * NTILES;
    for (int j = i; j < total_tm; j += gridDim.x * blockDim.x)
        tmax[j] = 0u;
    int total_rc = M_ROWS * DM / 4;
    float4 z = make_float4(0.f, 0.f, 0.f, 0.f);
    for (int j = i; j < total_rc; j += gridDim.x * blockDim.x)
        reinterpret_cast<float4*>(recon)[j] = z;
}

// ---------------------------------------------------------------------------
// Conversion kernels
// ---------------------------------------------------------------------------
__global__ __launch_bounds__(256) void to_f16_scaled_kernel(
    const float* __restrict__ src, __half* __restrict__ dst, float scale, int n4)
{
    int i = blockIdx.x * blockDim.x + threadIdx.x;
    if (i >= n4) return;
    float4 v = reinterpret_cast<const float4*>(src)[i];
    ushort4 hv;
    hv.x = __half_as_ushort(__float2half_rn(v.x * scale));
    hv.y = __half_as_ushort(__float2half_rn(v.y * scale));
    hv.z = __half_as_ushort(__float2half_rn(v.z * scale));
    hv.w = __half_as_ushort(__float2half_rn(v.w * scale));
    reinterpret_cast<ushort4*>(dst)[i] = hv;
}

// dict [N_ATOMS][DM] fp32 -> Df fp16 (same layout) + DTf fp16 (transposed).
__global__ __launch_bounds__(256) void convert_dict_kernel(
    const float* __restrict__ dict, __half* __restrict__ Df,
    __half* __restrict__ DTf)
{
    __shared__ float t[32][33];
    const int bx = blockIdx.x;   // DM tile
    const int by = blockIdx.y;   // atom tile
    const int tx = threadIdx.x;
    const int ty = threadIdx.y;
    #pragma unroll
    for (int k = 0; k < 32; k += 8) {
        float v = dict[(size_t)(by * 32 + ty + k) * DM + bx * 32 + tx];
        t[ty + k][tx] = v;
        Df[(size_t)(by * 32 + ty + k) * DM + bx * 32 + tx] = __float2half_rn(v);
    }
    __syncthreads();
    #pragma unroll
    for (int k = 0; k < 32; k += 8) {
        size_t o = (size_t)(bx * 32 + ty + k) * N_ATOMS + by * 32 + tx;
        DTf[o] = __float2half_rn(t[tx][ty + k]);
    }
}

// ---------------------------------------------------------------------------
// Unified 1-term fp16 GEMM via ldmatrix + mma.sync, BK=32, 4-stage cp.async.
// out tile 128x128 = A[M,K] · B[N,K]^T   (split-K along gridDim.z)
// MASK=true : out is __half WEIGHT w = 2^s (A pre-scaled by log2e), masked->0;
//             epilogue accumulates per-row sum (atomicAdd) and PER-TILE max
//             (atomicMax on float bits) of the fp16-rounded weights.
// MASK=false: out is float; row scaled by invp[row]; if gridDim.z>1 the
//             partial is accumulated with atomicAdd (output pre-zeroed).
// 128 threads = 4 warps (2x2) of 64x64.
// smem rows: 64B data + 16B pad (80B) — conflict-free LDSM phases.
// ---------------------------------------------------------------------------
#define ROWB     80
#define TILE_B   (128 * ROWB)          // 10240
#define STAGE    (2 * TILE_B)          // 20480
#define NSTAGES  4
#define SMEMG    (NSTAGES * STAGE)     // 81920

template <bool MASK>
__global__ __launch_bounds__(128, 2) void gemm_f16(
    const __half* __restrict__ A, const __half* __restrict__ B, int Kdim,
    const int* __restrict__ mask, const float* __restrict__ invp,
    float* __restrict__ rsum, unsigned* __restrict__ tmax,
    void* __restrict__ outp, int out_ld)
{
    extern __shared__ char smem[];
    const uint32_t sbase = smem_to_u32(smem);
    const int tid  = threadIdx.x;
    const int warp = tid >> 5;
    const int lane = tid & 31;
    const int bm = blockIdx.y * 128;
    const int bn = blockIdx.x * 128;
    const int wm = (warp & 1) * 64;
    const int wn = (warp >> 1) * 64;

    // split-K range
    const int ksz = Kdim / gridDim.z;
    const int cbase = (blockIdx.z * ksz) >> 5;
    const int ncs = ksz >> 5;

    // ldmatrix per-thread address components
    const int a_row = wm + (lane & 15);
    const int a_kh  = (lane >> 4) * 16;
    const int b_row = wn + ((lane >> 4) << 3) + (lane & 7);
    const int b_kh  = ((lane >> 3) & 1) * 16;

    float acc[4][8][4];
    #pragma unroll
    for (int mt = 0; mt < 4; mt++)
        #pragma unroll
        for (int nt = 0; nt < 8; nt++)
            #pragma unroll
            for (int r = 0; r < 4; r++) acc[mt][nt][r] = 0.0f;

    #define ISSUEG(cc, buf) do { \
        const int k0_ = (cc) << 5; \
        _Pragma("unroll") \
        for (int p = 0; p < 4; p++) { \
            const int v_   = tid + p * 128; \
            const int row_ = v_ >> 2; \
            const int c16_ = v_ & 3; \
            const uint32_t dst_ = sbase + (buf) * STAGE \
                                + row_ * ROWB + c16_ * 16; \
            const size_t ga_ = (size_t)(bm + row_) * Kdim + k0_ + c16_ * 8; \
            const size_t gb_ = (size_t)(bn + row_) * Kdim + k0_ + c16_ * 8; \
            CP16(dst_ + 0 * TILE_B, A + ga_); \
            CP16(dst_ + 1 * TILE_B, B + gb_); \
        } \
        CP_COMMIT(); \
    } while (0)

    ISSUEG(cbase + 0, 0);
    ISSUEG(cbase + 1, 1);
    ISSUEG(cbase + 2, 2);

    for (int i = 0; i < ncs; i++) {
        CP_WAIT2();          // chunk i resident (<=2 younger groups pending)
        __syncthreads();     // all warps past compute of chunk i-1
        if (i + 3 < ncs) ISSUEG(cbase + i + 3, (i + 3) & 3);

        const uint32_t sA = sbase + (i & 3) * STAGE;
        const uint32_t sB = sA + TILE_B;

        #pragma unroll
        for (int ks = 0; ks < 2; ks++) {
            const uint32_t kb0 = ks * 32;

            uint32_t a[4][4], b[8][2];
            #pragma unroll
            for (int mt = 0; mt < 4; mt++) {
                const uint32_t ad = sA + (a_row + mt * 16) * ROWB + a_kh + kb0;
                LDSM4(a[mt][0], a[mt][1], a[mt][2], a[mt][3], ad);
            }
            #pragma unroll
            for (int p = 0; p < 4; p++) {
                const uint32_t bd = sB + (b_row + p * 16) * ROWB + b_kh + kb0;
                LDSM4(b[2 * p][0], b[2 * p][1], b[2 * p + 1][0], b[2 * p + 1][1], bd);
            }
            #pragma unroll
            for (int nt = 0; nt < 8; nt++)
                #pragma unroll
                for (int mt = 0; mt < 4; mt++)
                    mma16816_f16(acc[mt][nt], a[mt], b[nt]);
        }
    }
    #undef ISSUEG

    // Epilogue
    const int lr = lane >> 2;
    const bool splitk = (!MASK) && (gridDim.z > 1);
    #pragma unroll
    for (int mt = 0; mt < 4; mt++) {
        #pragma unroll
        for (int half = 0; half < 2; half++) {
            const int rloc = bm + wm + mt * 16 + lr + half * 8;
            float inv = 1.0f;
            if (!MASK) inv = invp[rloc];
            const size_t rg = (size_t)rloc;
            float rsum_l = 0.0f, rmax_l = 0.0f;
            #pragma unroll
            for (int nt = 0; nt < 8; nt++) {
                const size_t o = rg * (size_t)out_ld
                               + (bn + wn + nt * 8 + (lane & 3) * 2);
                if (MASK) {
                    // fused softmax numerator: w = 2^s (A pre-scaled), mask->0
                    int2 mv = *reinterpret_cast<const int2*>(mask + o);
                    float2 v;
                    v.x = mv.x ? ex2f(acc[mt][nt][half * 2 + 0]) : 0.0f;
                    v.y = mv.y ? ex2f(acc[mt][nt][half * 2 + 1]) : 0.0f;
                    __half2 h2 = __float22half2_rn(v);
                    *reinterpret_cast<__half2*>((__half*)outp + o) = h2;
                    // accumulate from the ROUNDED values (consistency)
                    float2 vr = __half22float2(h2);
                    rsum_l += vr.x + vr.y;
                    rmax_l = fmaxf(rmax_l, fmaxf(vr.x, vr.y));
                } else {
                    float vx = acc[mt][nt][half * 2 + 0] * inv;
                    float vy = acc[mt][nt][half * 2 + 1] * inv;
                    float* op = (float*)outp + o;
                    if (splitk) {
                        atomicAdd(op + 0, vx);
                        atomicAdd(op + 1, vy);
                    } else {
                        *reinterpret_cast<float2*>(op) = make_float2(vx, vy);
                    }
                }
            }
            if (MASK) {
                // quad reduce (lanes with same lr hold same row)
                rsum_l += __shfl_xor_sync(0xffffffffu, rsum_l, 1);
                rsum_l += __shfl_xor_sync(0xffffffffu, rsum_l, 2);
                rmax_l = fmaxf(rmax_l, __shfl_xor_sync(0xffffffffu, rmax_l, 1));
                rmax_l = fmaxf(rmax_l, __shfl_xor_sync(0xffffffffu, rmax_l, 2));
                if ((lane & 3) == 0) {
                    atomicAdd(rsum + rloc, rsum_l);
                    atomicMax(tmax + (size_t)rloc * NTILES + blockIdx.x,
                              __float_as_uint(rmax_l));
                }
            }
        }
    }
}

// ---------------------------------------------------------------------------
// Exact argmax, one block (256 thr) per row, using per-tile maxima:
// 1) reduce 128 tile maxima -> global max, thresh = max*CANDF
// 2) scan ONLY tiles whose max >= thresh (usually 1-2) for candidates
// 3) exact fp32 dot per candidate (block-wide over DM), winner by
//    (value, then smaller index). Also publishes invp = 1/sum.
// ---------------------------------------------------------------------------
#define BETTER(v, i, V, I) ((v) > (V) || ((v) == (V) && (i) < (I)))

__global__ __launch_bounds__(256) void argmax_rescue_kernel(
    const __half* __restrict__ Wf, const float* __restrict__ X,
    const float* __restrict__ Dict, const float* __restrict__ rsum,
    const unsigned* __restrict__ tmax, float* __restrict__ invp,
    float* __restrict__ argmax_out)
{
    const int row = blockIdx.x;
    const __half* wf = Wf + (size_t)row * N_ATOMS;
    const int tid = threadIdx.x;

    __shared__ float sred[256];
    __shared__ int   stile[MAXCAND];
    __shared__ int   stcount;
    __shared__ int   scand[MAXCAND];
    __shared__ int   scount;
    __shared__ float sthresh;

    if (tid == 0) { stcount = 0; scount = 0; }

    // 1) global max over tile maxima
    float tm = (tid < NTILES)
        ? __uint_as_float(tmax[(size_t)row * NTILES + tid]) : 0.0f;
    sred[tid] = tm;
    __syncthreads();
    for (int off = 128; off > 0; off >>= 1) {
        if (tid < off) sred[tid] = fmaxf(sred[tid], sred[tid + off]);
        __syncthreads();
    }
    if (tid == 0) sthresh = sred[0] * CANDF;
    __syncthreads();
    const float thresh = sthresh;

    // 2) qualifying tiles
    if (tid < NTILES && tm >= thresh) {
        int slot = atomicAdd(&stcount, 1);
        if (slot < MAXCAND) stile[slot] = tid;
    }
    __syncthreads();
    int tcnt = stcount; if (tcnt > MAXCAND) tcnt = MAXCAND;

    // scan qualifying tiles for candidates (128 weights per tile)
    for (int j = 0; j < tcnt; j++) {
        const int base = stile[j] * 128;
        if (tid < 128) {
            float w = __half2float(wf[base + tid]);
            if (w >= thresh) {
                int slot = atomicAdd(&scount, 1);
                if (slot < MAXCAND) scand[slot] = base + tid;
            }
        }
    }
    __syncthreads();
    int cnt = scount; if (cnt > MAXCAND) cnt = MAXCAND;

    // 3) exact fp32 dot per candidate; block-wide over DM (256 x 4 = 1024)
    const float* x = X + (size_t)row * DM;
    float4 xv = *reinterpret_cast<const float4*>(x + tid * 4);
    float bv = -INFINITY; int bi = 0x7fffffff;
    for (int j = 0; j < cnt; j++) {
        const int ci = scand[j];
        float4 dv = *reinterpret_cast<const float4*>(
            Dict + (size_t)ci * DM + tid * 4);
        sred[tid] = xv.x * dv.x + xv.y * dv.y + xv.z * dv.z + xv.w * dv.w;
        __syncthreads();
        for (int off = 128; off > 0; off >>= 1) {
            if (tid < off) sred[tid] += sred[tid + off];
            __syncthreads();
        }
        const float sc = sred[0];
        if (BETTER(sc, ci, bv, bi)) { bv = sc; bi = ci; }
        __syncthreads();
    }
    if (tid == 0) {
        argmax_out[row] = (float)bi;
        invp[row] = 1.0f / rsum[row];
    }
}

// ---------------------------------------------------------------------------
// Launch
// ---------------------------------------------------------------------------
extern "C" void kernel_launch(void* const* d_in, const int* in_sizes, int n_in,
                              void* d_out, int out_size)
{
    const float* X    = (const float*)d_in[0];
    const float* Dict = (const float*)d_in[1];
    const int*   mask = (const int*)d_in[2];
    float* out = (float*)d_out;

    __half *Xf, *Df, *DTf, *Wf;
    cudaGetSymbolAddress((void**)&Xf, g_Xf);
    cudaGetSymbolAddress((void**)&Df, g_Df);
    cudaGetSymbolAddress((void**)&DTf, g_DTf);
    cudaGetSymbolAddress((void**)&Wf, g_Wf);
    float* rsum; cudaGetSymbolAddress((void**)&rsum, g_sum);
    unsigned* tmax; cudaGetSymbolAddress((void**)&tmax, g_tmax);
    float* invp; cudaGetSymbolAddress((void**)&invp, g_inv);

    float* recon_out  = out;
    float* argmax_out = out + (size_t)M_ROWS * DM;

    static bool attr_set = false;
    if (!attr_set) {
        cudaFuncSetAttribute(gemm_f16<true>,
                             cudaFuncAttributeMaxDynamicSharedMemorySize, SMEMG);
        cudaFuncSetAttribute(gemm_f16<false>,
                             cudaFuncAttributeMaxDynamicSharedMemorySize, SMEMG);
        attr_set = true;
    }

    // 0) zero per-row sums, tile maxima, and recon output (split-K target)
    init_kernel<<<1024, 256>>>(rsum, tmax, recon_out);

    // 1) fp16 conversions: X*log2e, dict (K-major + transposed, single read)
    {
        int n4x = (M_ROWS * DM) / 4;
        to_f16_scaled_kernel<<<(n4x + 255) / 256, 256>>>(X, Xf, LOG2E, n4x);
        dim3 grid(DM / 32, N_ATOMS / 32), blk(32, 8);
        convert_dict_kernel<<<grid, blk>>>(Dict, Df, DTf);
    }

    // 2) fused scores+exp GEMM: Wf = 2^(Xf · Df^T), masked -> 0,
    //    with per-row sum and per-tile max atomics
    {
        dim3 grid(N_ATOMS / 128, M_ROWS / 128, 1);
        gemm_f16<true><<<grid, 128, SMEMG>>>(
            Xf, Df, DM, mask, nullptr, rsum, tmax, Wf, N_ATOMS);
    }

    // 3) exact argmax via tile maxima (tiny traffic) + invp
    argmax_rescue_kernel<<<M_ROWS, 256>>>(
        Wf, X, Dict, rsum, tmax, invp, argmax_out);

    // 4) reconstruction = (Wf · DTf) * inv[row], split-K=4 with atomic accum
    {
        dim3 grid(DM / 128, M_ROWS / 128, KSPLIT);
        gemm_f16<false><<<grid, 128, SMEMG>>>(
            Wf, DTf, N_ATOMS, nullptr, invp, nullptr, nullptr, recon_out, DM);
    }
}